// round 2
// baseline (speedup 1.0000x reference)
#include <cuda_runtime.h>
#include <cuda_bf16.h>

#define N_NODES 50000
#define E_EDGES 800000
#define D_INP   128
#define D_HID   256

// ---------------- scratch (device globals; no allocation allowed) ----------------
__device__ __align__(256) float g_aggX[(size_t)N_NODES * D_INP];   // aggregated x (shared by both channels)
__device__ __align__(256) float g_h   [(size_t)N_NODES * D_HID];   // current hidden
__device__ __align__(256) float g_agg [(size_t)N_NODES * D_HID];   // aggregated hidden
__device__ __align__(256) float g_w   [E_EDGES];                   // per-edge norm weight (CSR order)
__device__ __align__(256) int   g_col [E_EDGES];                   // CSR column (src node)
__device__ int   g_cnt[N_NODES];
__device__ int   g_rowptr[N_NODES + 1];
__device__ int   g_pos[N_NODES];
__device__ float g_dinv[N_NODES];
__device__ int   g_mode32;     // 1 = indices are int32, 0 = int64 (read low words)

// index helper: element idx of a logical int array that may be i32 or i64
__device__ __forceinline__ int idx_at(const int* __restrict__ p32, int mode32, int idx) {
    return mode32 ? p32[idx] : p32[2 * (size_t)idx];
}

// ---------------- dtype detection (graph-capturable, deterministic) ----------------
// If edge is int64 (non-negative values < 2^31), every odd 32-bit word is 0.
// If edge is int32, odd words are random node ids in [0, 50000) -> ~surely nonzero.
__global__ void detect_kernel(const int* __restrict__ e32) {
    __shared__ int any;
    if (threadIdx.x == 0) any = 0;
    __syncthreads();
    // sample 1024 odd words spread across the buffer (all within first E int32 words)
    int i = threadIdx.x;                       // 1024 threads
    int w = e32[2 * (i * 391) + 1];            // 2*(i*391)+1 < 800000 for i<1024
    if (w != 0) atomicOr(&any, 1);
    __syncthreads();
    if (threadIdx.x == 0) g_mode32 = any;
}

// ---------------- graph preprocessing ----------------
__global__ void zero_cnt_kernel() {
    int i = blockIdx.x * blockDim.x + threadIdx.x;
    if (i < N_NODES) g_cnt[i] = 0;
}

__global__ void count_kernel(const int* __restrict__ e32) {
    int e = blockIdx.x * blockDim.x + threadIdx.x;
    if (e < E_EDGES) {
        int d = idx_at(e32, g_mode32, E_EDGES + e);
        atomicAdd(&g_cnt[d], 1);
    }
}

__global__ void dinv_kernel() {
    int i = blockIdx.x * blockDim.x + threadIdx.x;
    if (i < N_NODES) {
        float deg = (float)(g_cnt[i] + 1);   // +1 self-loop
        g_dinv[i] = rsqrtf(deg);
    }
}

// single-block exclusive scan over g_cnt -> g_rowptr, g_pos
__global__ void scan_kernel() {
    __shared__ int sh[1024];
    int t = threadIdx.x;
    int offset = 0;
    for (int base = 0; base < N_NODES; base += 1024) {
        int idx = base + t;
        int v = (idx < N_NODES) ? g_cnt[idx] : 0;
        sh[t] = v;
        __syncthreads();
        #pragma unroll
        for (int d = 1; d < 1024; d <<= 1) {
            int add = (t >= d) ? sh[t - d] : 0;
            __syncthreads();
            sh[t] += add;
            __syncthreads();
        }
        if (idx < N_NODES) {
            int excl = offset + sh[t] - v;
            g_rowptr[idx] = excl;
            g_pos[idx]    = excl;
        }
        offset += sh[1023];
        __syncthreads();
    }
    if (t == 0) g_rowptr[N_NODES] = offset;
}

__global__ void fill_kernel(const int* __restrict__ e32) {
    int e = blockIdx.x * blockDim.x + threadIdx.x;
    if (e < E_EDGES) {
        int m = g_mode32;
        int s = idx_at(e32, m, e);
        int d = idx_at(e32, m, E_EDGES + e);
        int p = atomicAdd(&g_pos[d], 1);
        g_col[p] = s;
        g_w[p]   = g_dinv[s] * g_dinv[d];
    }
}

// ---------------- aggregation: out[v] = dinv[v]^2 * h[v] + sum_e w_e * h[src_e] ----------------
template <int D>
__global__ void aggregate_kernel(const float* __restrict__ h, float* __restrict__ out) {
    int v = blockIdx.x;
    int t = threadIdx.x;                      // D/4 threads
    const float4* h4 = (const float4*)h;
    float dv = g_dinv[v];
    float sw = dv * dv;
    float4 hv = h4[(size_t)v * (D / 4) + t];
    float4 acc = make_float4(sw * hv.x, sw * hv.y, sw * hv.z, sw * hv.w);
    int beg = g_rowptr[v];
    int end = g_rowptr[v + 1];
    for (int j = beg; j < end; ++j) {
        int   c  = __ldg(&g_col[j]);
        float wj = __ldg(&g_w[j]);
        float4 hc = h4[(size_t)c * (D / 4) + t];
        acc.x += wj * hc.x;
        acc.y += wj * hc.y;
        acc.z += wj * hc.z;
        acc.w += wj * hc.w;
    }
    ((float4*)out)[(size_t)v * (D / 4) + t] = acc;
}

// ---------------- GEMM + bias + (relu(t)+t) epilogue ----------------
// C[N,256] = A[N,K] @ W[K,256]; BM=128 BN=64 BK=16, 256 threads, 8x4 per thread
template <int K>
__launch_bounds__(256)
__global__ void gemm_relu_res(const float* __restrict__ A, const float* __restrict__ W,
                              const float* __restrict__ bias, float* __restrict__ C) {
    __shared__ float As[16][128];
    __shared__ float Ws[16][64];
    int tid = threadIdx.x;
    int m0 = blockIdx.x * 128;
    int n0 = blockIdx.y * 64;

    float acc[8][4];
    #pragma unroll
    for (int i = 0; i < 8; i++)
        #pragma unroll
        for (int j = 0; j < 4; j++) acc[i][j] = 0.f;

    int arow = tid >> 2;            // 0..63
    int acol = (tid & 3) << 2;      // 0,4,8,12
    int wrow = tid >> 4;            // 0..15
    int wcol = (tid & 15) << 2;     // 0..60
    int ty = tid >> 4;              // m-group 0..15
    int tx = tid & 15;              // n-group 0..15

    for (int k0 = 0; k0 < K; k0 += 16) {
        #pragma unroll
        for (int half = 0; half < 2; ++half) {
            int m = m0 + arow + half * 64;
            float4 av = (m < N_NODES)
                      ? *(const float4*)&A[(size_t)m * K + k0 + acol]
                      : make_float4(0.f, 0.f, 0.f, 0.f);
            As[acol + 0][arow + half * 64] = av.x;
            As[acol + 1][arow + half * 64] = av.y;
            As[acol + 2][arow + half * 64] = av.z;
            As[acol + 3][arow + half * 64] = av.w;
        }
        *(float4*)&Ws[wrow][wcol] =
            *(const float4*)&W[(size_t)(k0 + wrow) * 256 + n0 + wcol];
        __syncthreads();

        #pragma unroll
        for (int k = 0; k < 16; ++k) {
            float a[8], b[4];
            #pragma unroll
            for (int i = 0; i < 8; i++) a[i] = As[k][ty * 8 + i];
            #pragma unroll
            for (int j = 0; j < 4; j++) b[j] = Ws[k][tx * 4 + j];
            #pragma unroll
            for (int i = 0; i < 8; i++)
                #pragma unroll
                for (int j = 0; j < 4; j++)
                    acc[i][j] += a[i] * b[j];
        }
        __syncthreads();
    }

    #pragma unroll
    for (int i = 0; i < 8; i++) {
        int m = m0 + ty * 8 + i;
        if (m < N_NODES) {
            #pragma unroll
            for (int j = 0; j < 4; j++) {
                int n = n0 + tx * 4 + j;
                float t = acc[i][j] + bias[n];
                float r = fmaxf(t, 0.f) + t;   // relu(t) + t
                C[(size_t)m * 256 + n] = r;
            }
        }
    }
}

// ---------------- LayerNorm over last dim (256) ----------------
__global__ void ln_kernel(const float* __restrict__ h, const float* __restrict__ lw,
                          const float* __restrict__ lb, float* __restrict__ out) {
    int row = blockIdx.x;
    int t = threadIdx.x;
    __shared__ float red[256];
    float v = h[(size_t)row * 256 + t];
    red[t] = v;
    __syncthreads();
    #pragma unroll
    for (int s = 128; s > 0; s >>= 1) {
        if (t < s) red[t] += red[t + s];
        __syncthreads();
    }
    float mean = red[0] * (1.f / 256.f);
    __syncthreads();
    float d = v - mean;
    red[t] = d * d;
    __syncthreads();
    #pragma unroll
    for (int s = 128; s > 0; s >>= 1) {
        if (t < s) red[t] += red[t + s];
        __syncthreads();
    }
    float var = red[0] * (1.f / 256.f);
    out[(size_t)row * 256 + t] = d * rsqrtf(var + 1e-6f) * lw[t] + lb[t];
}

__global__ void batchs_kernel(const int* __restrict__ b32, float* __restrict__ out) {
    int i = blockIdx.x * blockDim.x + threadIdx.x;
    if (i < N_NODES) {
        float bv = (float)idx_at(b32, g_mode32, i);
        out[i]           = bv;   // channel 0
        out[N_NODES + i] = bv;   // channel 1
    }
}

// ---------------- launcher ----------------
extern "C" void kernel_launch(void* const* d_in, const int* in_sizes, int n_in,
                              void* d_out, int out_size) {
    const float* x    = (const float*)d_in[0];
    const int*   e32  = (const int*)d_in[1];    // edge, int32 or int64 (auto-detected)
    const int*   b32  = (const int*)d_in[2];    // batch, same dtype as edge
    const float* W0 = (const float*)d_in[3];
    const float* b0 = (const float*)d_in[4];
    const float* W1 = (const float*)d_in[5];
    const float* b1 = (const float*)d_in[6];
    const float* W2 = (const float*)d_in[7];
    const float* b2 = (const float*)d_in[8];
    const float* lnw = (const float*)d_in[9];
    const float* lnb = (const float*)d_in[10];
    float* out = (float*)d_out;

    float *p_aggX, *p_h, *p_agg;
    cudaGetSymbolAddress((void**)&p_aggX, g_aggX);
    cudaGetSymbolAddress((void**)&p_h,    g_h);
    cudaGetSymbolAddress((void**)&p_agg,  g_agg);

    const int TB = 256;
    detect_kernel <<<1, 1024>>>(e32);
    zero_cnt_kernel<<<(N_NODES + TB - 1) / TB, TB>>>();
    count_kernel  <<<(E_EDGES + TB - 1) / TB, TB>>>(e32);
    dinv_kernel   <<<(N_NODES + TB - 1) / TB, TB>>>();
    scan_kernel   <<<1, 1024>>>();
    fill_kernel   <<<(E_EDGES + TB - 1) / TB, TB>>>(e32);

    // shared layer-0 aggregation of x (128-dim), used by both channels
    aggregate_kernel<128><<<N_NODES, 32>>>(x, p_aggX);

    dim3 ggrid((N_NODES + 127) / 128, 256 / 64);
    for (int c = 0; c < 2; ++c) {
        gemm_relu_res<128><<<ggrid, 256>>>(p_aggX, W0 + (size_t)c * 128 * 256,
                                           b0 + c * 256, p_h);
        aggregate_kernel<256><<<N_NODES, 64>>>(p_h, p_agg);
        gemm_relu_res<256><<<ggrid, 256>>>(p_agg, W1 + (size_t)c * 256 * 256,
                                           b1 + c * 256, p_h);
        aggregate_kernel<256><<<N_NODES, 64>>>(p_h, p_agg);
        gemm_relu_res<256><<<ggrid, 256>>>(p_agg, W2 + (size_t)c * 256 * 256,
                                           b2 + c * 256, p_h);
        ln_kernel<<<N_NODES, 256>>>(p_h, lnw, lnb, out + (size_t)c * N_NODES * 256);
    }
    batchs_kernel<<<(N_NODES + TB - 1) / TB, TB>>>(b32, out + (size_t)2 * N_NODES * 256);
}

// round 3
// speedup vs baseline: 1.6149x; 1.6149x over previous
#include <cuda_runtime.h>
#include <cuda_bf16.h>

#define N_NODES 50000
#define E_EDGES 800000
#define D_INP   128
#define D_HID   256

// ---------------- scratch (device globals; no allocation allowed) ----------------
__device__ __align__(256) float g_aggX[(size_t)N_NODES * D_INP];   // aggregated x (shared by both channels)
__device__ __align__(256) float g_h   [(size_t)N_NODES * D_HID];   // current hidden
__device__ __align__(256) float g_agg [(size_t)N_NODES * D_HID];   // aggregated hidden
__device__ __align__(256) float g_w   [E_EDGES];                   // per-edge norm weight (CSR order)
__device__ __align__(256) int   g_col [E_EDGES];                   // CSR column (src node)
__device__ int   g_cnt[N_NODES];
__device__ int   g_rowptr[N_NODES + 1];
__device__ int   g_pos[N_NODES];
__device__ float g_dinv[N_NODES];
__device__ int   g_mode32;     // 1 = indices are int32, 0 = int64 (read low words)

__device__ __forceinline__ int idx_at(const int* __restrict__ p32, int mode32, int idx) {
    return mode32 ? p32[idx] : p32[2 * (size_t)idx];
}

__device__ __forceinline__ unsigned f2tf(float f) {
    unsigned u;
    asm("cvt.rna.tf32.f32 %0, %1;" : "=r"(u) : "f"(f));
    return u;
}

// ---------------- dtype detection (graph-capturable, deterministic) ----------------
__global__ void detect_kernel(const int* __restrict__ e32) {
    __shared__ int any;
    if (threadIdx.x == 0) any = 0;
    __syncthreads();
    int i = threadIdx.x;                       // 1024 threads
    int w = e32[2 * (i * 391) + 1];            // stays within first E int32 words
    if (w != 0) atomicOr(&any, 1);
    __syncthreads();
    if (threadIdx.x == 0) g_mode32 = any;
}

// ---------------- graph preprocessing ----------------
__global__ void zero_cnt_kernel() {
    int i = blockIdx.x * blockDim.x + threadIdx.x;
    if (i < N_NODES) g_cnt[i] = 0;
}

__global__ void count_kernel(const int* __restrict__ e32) {
    int e = blockIdx.x * blockDim.x + threadIdx.x;
    if (e < E_EDGES) {
        int d = idx_at(e32, g_mode32, E_EDGES + e);
        atomicAdd(&g_cnt[d], 1);
    }
}

__global__ void dinv_kernel() {
    int i = blockIdx.x * blockDim.x + threadIdx.x;
    if (i < N_NODES) {
        float deg = (float)(g_cnt[i] + 1);   // +1 self-loop
        g_dinv[i] = rsqrtf(deg);
    }
}

// single-block exclusive scan over g_cnt -> g_rowptr, g_pos
__global__ void scan_kernel() {
    __shared__ int sh[1024];
    int t = threadIdx.x;
    int offset = 0;
    for (int base = 0; base < N_NODES; base += 1024) {
        int idx = base + t;
        int v = (idx < N_NODES) ? g_cnt[idx] : 0;
        sh[t] = v;
        __syncthreads();
        #pragma unroll
        for (int d = 1; d < 1024; d <<= 1) {
            int add = (t >= d) ? sh[t - d] : 0;
            __syncthreads();
            sh[t] += add;
            __syncthreads();
        }
        if (idx < N_NODES) {
            int excl = offset + sh[t] - v;
            g_rowptr[idx] = excl;
            g_pos[idx]    = excl;
        }
        offset += sh[1023];
        __syncthreads();
    }
    if (t == 0) g_rowptr[N_NODES] = offset;
}

__global__ void fill_kernel(const int* __restrict__ e32) {
    int e = blockIdx.x * blockDim.x + threadIdx.x;
    if (e < E_EDGES) {
        int m = g_mode32;
        int s = idx_at(e32, m, e);
        int d = idx_at(e32, m, E_EDGES + e);
        int p = atomicAdd(&g_pos[d], 1);
        g_col[p] = s;
        g_w[p]   = g_dinv[s] * g_dinv[d];
    }
}

// ---------------- aggregation: out[v] = dinv[v]^2 * h[v] + sum_e w_e * h[src_e] ----------------
template <int D>
__global__ void aggregate_kernel(const float* __restrict__ h, float* __restrict__ out) {
    int v = blockIdx.x;
    int t = threadIdx.x;                      // D/4 threads
    const float4* h4 = (const float4*)h;
    float dv = g_dinv[v];
    float sw = dv * dv;
    float4 hv = h4[(size_t)v * (D / 4) + t];
    float4 acc = make_float4(sw * hv.x, sw * hv.y, sw * hv.z, sw * hv.w);
    int beg = g_rowptr[v];
    int end = g_rowptr[v + 1];
    for (int j = beg; j < end; ++j) {
        int   c  = __ldg(&g_col[j]);
        float wj = __ldg(&g_w[j]);
        float4 hc = h4[(size_t)c * (D / 4) + t];
        acc.x += wj * hc.x;
        acc.y += wj * hc.y;
        acc.z += wj * hc.z;
        acc.w += wj * hc.w;
    }
    ((float4*)out)[(size_t)v * (D / 4) + t] = acc;
}

// ---------------- tf32 tensor-core GEMM + bias + (relu(t)+t) epilogue ----------------
// C[N,256] = A[N,K] @ W[K,256]; BM=128 BN=128 BK=32, 8 warps (32x64 warp tiles)
template <int K>
__launch_bounds__(256)
__global__ void gemm_tf32(const float* __restrict__ A, const float* __restrict__ W,
                          const float* __restrict__ bias, float* __restrict__ C) {
    // As: [k/4 chunk (8)][m (128)][k%4 (4)]  -> fragment loads conflict-free
    __shared__ __align__(16) unsigned As[8 * 128 * 4];
    // Bs: [k (32)][n] with stride 136        -> 136 % 32 = 8 -> conflict-free loads
    __shared__ __align__(16) unsigned Bs[32 * 136];

    const int tid  = threadIdx.x;
    const int lane = tid & 31, wid = tid >> 5;
    const int g  = lane >> 2, t4 = lane & 3;
    const int m0 = blockIdx.x * 128, n0 = blockIdx.y * 128;
    const int wr = (wid & 3) * 32;     // warp row base
    const int wc = (wid >> 2) * 64;    // warp col base

    float acc[2][8][4];
    #pragma unroll
    for (int mt = 0; mt < 2; mt++)
        #pragma unroll
        for (int nt = 0; nt < 8; nt++)
            #pragma unroll
            for (int r = 0; r < 4; r++) acc[mt][nt][r] = 0.f;

    const int la_row = tid >> 3;       // 0..31 (m base; +i*32)
    const int la_ch  = tid & 7;        // k/4 chunk
    const int lb_k   = tid >> 5;       // 0..7  (k base; +i*8)
    const int lb_n   = (tid & 31) * 4; // n

    float4 aR[4], bR[4];

    auto fetch = [&](int k0) {
        #pragma unroll
        for (int i = 0; i < 4; i++) {
            int m = m0 + la_row + i * 32;
            aR[i] = (m < N_NODES)
                  ? *(const float4*)&A[(size_t)m * K + k0 + la_ch * 4]
                  : make_float4(0.f, 0.f, 0.f, 0.f);
        }
        #pragma unroll
        for (int i = 0; i < 4; i++) {
            int k = k0 + lb_k + i * 8;
            bR[i] = *(const float4*)&W[(size_t)k * 256 + n0 + lb_n];
        }
    };

    fetch(0);
    for (int k0 = 0; k0 < K; k0 += 32) {
        #pragma unroll
        for (int i = 0; i < 4; i++) {
            uint4 v = make_uint4(f2tf(aR[i].x), f2tf(aR[i].y), f2tf(aR[i].z), f2tf(aR[i].w));
            *(uint4*)&As[(la_ch * 128 + la_row + i * 32) * 4] = v;
        }
        #pragma unroll
        for (int i = 0; i < 4; i++) {
            uint4 v = make_uint4(f2tf(bR[i].x), f2tf(bR[i].y), f2tf(bR[i].z), f2tf(bR[i].w));
            *(uint4*)&Bs[(lb_k + i * 8) * 136 + lb_n] = v;
        }
        __syncthreads();
        if (k0 + 32 < K) fetch(k0 + 32);

        #pragma unroll
        for (int kk = 0; kk < 4; kk++) {
            unsigned a[2][4];
            #pragma unroll
            for (int mt = 0; mt < 2; mt++) {
                int m = wr + mt * 16 + g;
                a[mt][0] = As[((2 * kk) * 128 + m) * 4 + t4];
                a[mt][1] = As[((2 * kk) * 128 + m + 8) * 4 + t4];
                a[mt][2] = As[((2 * kk + 1) * 128 + m) * 4 + t4];
                a[mt][3] = As[((2 * kk + 1) * 128 + m + 8) * 4 + t4];
            }
            #pragma unroll
            for (int nt = 0; nt < 8; nt++) {
                int n = wc + nt * 8 + g;
                unsigned b0 = Bs[(kk * 8 + t4) * 136 + n];
                unsigned b1 = Bs[(kk * 8 + t4 + 4) * 136 + n];
                #pragma unroll
                for (int mt = 0; mt < 2; mt++) {
                    asm volatile(
                        "mma.sync.aligned.m16n8k8.row.col.f32.tf32.tf32.f32 "
                        "{%0,%1,%2,%3}, {%4,%5,%6,%7}, {%8,%9}, {%0,%1,%2,%3};"
                        : "+f"(acc[mt][nt][0]), "+f"(acc[mt][nt][1]),
                          "+f"(acc[mt][nt][2]), "+f"(acc[mt][nt][3])
                        : "r"(a[mt][0]), "r"(a[mt][1]), "r"(a[mt][2]), "r"(a[mt][3]),
                          "r"(b0), "r"(b1));
                }
            }
        }
        __syncthreads();
    }

    // epilogue: bias + relu(t)+t
    #pragma unroll
    for (int mt = 0; mt < 2; mt++) {
        int r0 = m0 + wr + mt * 16 + g;
        #pragma unroll
        for (int nt = 0; nt < 8; nt++) {
            int n = n0 + wc + nt * 8 + 2 * t4;
            float bA = bias[n], bB = bias[n + 1];
            if (r0 < N_NODES) {
                float tx = acc[mt][nt][0] + bA;
                float ty = acc[mt][nt][1] + bB;
                *(float2*)&C[(size_t)r0 * 256 + n] =
                    make_float2(fmaxf(tx, 0.f) + tx, fmaxf(ty, 0.f) + ty);
            }
            int r1 = r0 + 8;
            if (r1 < N_NODES) {
                float tx = acc[mt][nt][2] + bA;
                float ty = acc[mt][nt][3] + bB;
                *(float2*)&C[(size_t)r1 * 256 + n] =
                    make_float2(fmaxf(tx, 0.f) + tx, fmaxf(ty, 0.f) + ty);
            }
        }
    }
}

// ---------------- LayerNorm over last dim (256) ----------------
__global__ void ln_kernel(const float* __restrict__ h, const float* __restrict__ lw,
                          const float* __restrict__ lb, float* __restrict__ out) {
    int row = blockIdx.x;
    int t = threadIdx.x;
    __shared__ float red[256];
    float v = h[(size_t)row * 256 + t];
    red[t] = v;
    __syncthreads();
    #pragma unroll
    for (int s = 128; s > 0; s >>= 1) {
        if (t < s) red[t] += red[t + s];
        __syncthreads();
    }
    float mean = red[0] * (1.f / 256.f);
    __syncthreads();
    float d = v - mean;
    red[t] = d * d;
    __syncthreads();
    #pragma unroll
    for (int s = 128; s > 0; s >>= 1) {
        if (t < s) red[t] += red[t + s];
        __syncthreads();
    }
    float var = red[0] * (1.f / 256.f);
    out[(size_t)row * 256 + t] = d * rsqrtf(var + 1e-6f) * lw[t] + lb[t];
}

__global__ void batchs_kernel(const int* __restrict__ b32, float* __restrict__ out) {
    int i = blockIdx.x * blockDim.x + threadIdx.x;
    if (i < N_NODES) {
        float bv = (float)idx_at(b32, g_mode32, i);
        out[i]           = bv;   // channel 0
        out[N_NODES + i] = bv;   // channel 1
    }
}

// ---------------- launcher ----------------
extern "C" void kernel_launch(void* const* d_in, const int* in_sizes, int n_in,
                              void* d_out, int out_size) {
    const float* x    = (const float*)d_in[0];
    const int*   e32  = (const int*)d_in[1];    // edge, int32 or int64 (auto-detected)
    const int*   b32  = (const int*)d_in[2];    // batch, same dtype as edge
    const float* W0 = (const float*)d_in[3];
    const float* b0 = (const float*)d_in[4];
    const float* W1 = (const float*)d_in[5];
    const float* b1 = (const float*)d_in[6];
    const float* W2 = (const float*)d_in[7];
    const float* b2 = (const float*)d_in[8];
    const float* lnw = (const float*)d_in[9];
    const float* lnb = (const float*)d_in[10];
    float* out = (float*)d_out;

    float *p_aggX, *p_h, *p_agg;
    cudaGetSymbolAddress((void**)&p_aggX, g_aggX);
    cudaGetSymbolAddress((void**)&p_h,    g_h);
    cudaGetSymbolAddress((void**)&p_agg,  g_agg);

    const int TB = 256;
    detect_kernel <<<1, 1024>>>(e32);
    zero_cnt_kernel<<<(N_NODES + TB - 1) / TB, TB>>>();
    count_kernel  <<<(E_EDGES + TB - 1) / TB, TB>>>(e32);
    dinv_kernel   <<<(N_NODES + TB - 1) / TB, TB>>>();
    scan_kernel   <<<1, 1024>>>();
    fill_kernel   <<<(E_EDGES + TB - 1) / TB, TB>>>(e32);

    // shared layer-0 aggregation of x (128-dim), used by both channels
    aggregate_kernel<128><<<N_NODES, 32>>>(x, p_aggX);

    dim3 ggrid((N_NODES + 127) / 128, 2);   // 128x128 output tiles over [50000 x 256]
    for (int c = 0; c < 2; ++c) {
        gemm_tf32<128><<<ggrid, 256>>>(p_aggX, W0 + (size_t)c * 128 * 256,
                                       b0 + c * 256, p_h);
        aggregate_kernel<256><<<N_NODES, 64>>>(p_h, p_agg);
        gemm_tf32<256><<<ggrid, 256>>>(p_agg, W1 + (size_t)c * 256 * 256,
                                       b1 + c * 256, p_h);
        aggregate_kernel<256><<<N_NODES, 64>>>(p_h, p_agg);
        gemm_tf32<256><<<ggrid, 256>>>(p_agg, W2 + (size_t)c * 256 * 256,
                                       b2 + c * 256, p_h);
        ln_kernel<<<N_NODES, 256>>>(p_h, lnw, lnb, out + (size_t)c * N_NODES * 256);
    }
    batchs_kernel<<<(N_NODES + TB - 1) / TB, TB>>>(b32, out + (size_t)2 * N_NODES * 256);
}

// round 4
// speedup vs baseline: 2.0620x; 1.2769x over previous
#include <cuda_runtime.h>
#include <cuda_bf16.h>

#define N_NODES 50000
#define E_EDGES 800000
#define D_INP   128
#define D_HID   256

// ---------------- scratch (device globals; no allocation allowed) ----------------
__device__ __align__(256) float g_aggX[(size_t)N_NODES * D_INP];   // aggregated x (shared)
__device__ __align__(256) float g_h  [(size_t)N_NODES * D_HID];    // channel-0 hidden
__device__ __align__(256) float g_agg[(size_t)N_NODES * D_HID];    // channel-0 aggregated
__device__ __align__(256) float g_h2 [(size_t)N_NODES * D_HID];    // channel-1 hidden
__device__ __align__(256) float g_agg2[(size_t)N_NODES * D_HID];   // channel-1 aggregated
__device__ __align__(256) int2  g_cw [E_EDGES];                    // CSR {src, w-bits}
__device__ int   g_cnt[N_NODES];
__device__ int   g_rowptr[N_NODES + 1];
__device__ int   g_pos[N_NODES];
__device__ float g_dinv[N_NODES];
__device__ int   g_mode32;     // 1 = indices are int32, 0 = int64 (read low words)

__device__ __forceinline__ int idx_at(const int* __restrict__ p32, int mode32, int idx) {
    return mode32 ? p32[idx] : p32[2 * (size_t)idx];
}

__device__ __forceinline__ unsigned f2tf(float f) {
    unsigned u;
    asm("cvt.rna.tf32.f32 %0, %1;" : "=r"(u) : "f"(f));
    return u;
}

// ---------------- dtype detection (graph-capturable, deterministic) ----------------
__global__ void detect_kernel(const int* __restrict__ e32) {
    __shared__ int any;
    if (threadIdx.x == 0) any = 0;
    __syncthreads();
    int i = threadIdx.x;                       // 1024 threads
    int w = e32[2 * (i * 391) + 1];            // stays within first E int32 words
    if (w != 0) atomicOr(&any, 1);
    __syncthreads();
    if (threadIdx.x == 0) g_mode32 = any;
}

// ---------------- graph preprocessing ----------------
__global__ void zero_cnt_kernel() {
    int i = blockIdx.x * blockDim.x + threadIdx.x;
    if (i < N_NODES) g_cnt[i] = 0;
}

__global__ void count_kernel(const int* __restrict__ e32) {
    int e = blockIdx.x * blockDim.x + threadIdx.x;
    if (e < E_EDGES) {
        int d = idx_at(e32, g_mode32, E_EDGES + e);
        atomicAdd(&g_cnt[d], 1);
    }
}

__global__ void dinv_kernel() {
    int i = blockIdx.x * blockDim.x + threadIdx.x;
    if (i < N_NODES) {
        float deg = (float)(g_cnt[i] + 1);   // +1 self-loop
        g_dinv[i] = rsqrtf(deg);
    }
}

// single-block exclusive scan over g_cnt -> g_rowptr, g_pos (warp-shuffle based)
__global__ void scan_kernel() {
    __shared__ int wsum[32];
    int t = threadIdx.x, lane = t & 31, w = t >> 5;
    int offset = 0;
    for (int base = 0; base < N_NODES; base += 1024) {
        int idx = base + t;
        int v = (idx < N_NODES) ? g_cnt[idx] : 0;
        int inc = v;
        #pragma unroll
        for (int d = 1; d < 32; d <<= 1) {
            int n = __shfl_up_sync(0xffffffffu, inc, d);
            if (lane >= d) inc += n;
        }
        if (lane == 31) wsum[w] = inc;
        __syncthreads();
        if (w == 0) {
            int s = wsum[lane];
            #pragma unroll
            for (int d = 1; d < 32; d <<= 1) {
                int n = __shfl_up_sync(0xffffffffu, s, d);
                if (lane >= d) s += n;
            }
            wsum[lane] = s;
        }
        __syncthreads();
        int wbase = (w == 0) ? 0 : wsum[w - 1];
        int total = wsum[31];
        if (idx < N_NODES) {
            int excl = offset + wbase + inc - v;
            g_rowptr[idx] = excl;
            g_pos[idx]    = excl;
        }
        offset += total;
        __syncthreads();
    }
    if (t == 0) g_rowptr[N_NODES] = offset;
}

__global__ void fill_kernel(const int* __restrict__ e32) {
    int e = blockIdx.x * blockDim.x + threadIdx.x;
    if (e < E_EDGES) {
        int m = g_mode32;
        int s = idx_at(e32, m, e);
        int d = idx_at(e32, m, E_EDGES + e);
        int p = atomicAdd(&g_pos[d], 1);
        g_cw[p] = make_int2(s, __float_as_int(g_dinv[s] * g_dinv[d]));
    }
}

// ---------------- aggregation: out[v] = dinv[v]^2 * h[v] + sum_e w_e * h[src_e] ----------------
template <int D>
__global__ void aggregate_kernel(const float* __restrict__ h, float* __restrict__ out) {
    int v = blockIdx.x;
    int t = threadIdx.x;                      // D/4 threads
    const float4* h4 = (const float4*)h;
    float dv = g_dinv[v];
    float sw = dv * dv;
    float4 hv = h4[(size_t)v * (D / 4) + t];
    float4 acc = make_float4(sw * hv.x, sw * hv.y, sw * hv.z, sw * hv.w);
    int beg = g_rowptr[v];
    int end = g_rowptr[v + 1];
    int j = beg;
    for (; j + 4 <= end; j += 4) {            // unrolled: 4 gathers in flight
        int2 cw0 = __ldg(&g_cw[j]);
        int2 cw1 = __ldg(&g_cw[j + 1]);
        int2 cw2 = __ldg(&g_cw[j + 2]);
        int2 cw3 = __ldg(&g_cw[j + 3]);
        float4 h0 = h4[(size_t)cw0.x * (D / 4) + t];
        float4 h1 = h4[(size_t)cw1.x * (D / 4) + t];
        float4 h2 = h4[(size_t)cw2.x * (D / 4) + t];
        float4 h3 = h4[(size_t)cw3.x * (D / 4) + t];
        float w0 = __int_as_float(cw0.y), w1 = __int_as_float(cw1.y);
        float w2 = __int_as_float(cw2.y), w3 = __int_as_float(cw3.y);
        acc.x += w0 * h0.x + w1 * h1.x + w2 * h2.x + w3 * h3.x;
        acc.y += w0 * h0.y + w1 * h1.y + w2 * h2.y + w3 * h3.y;
        acc.z += w0 * h0.z + w1 * h1.z + w2 * h2.z + w3 * h3.z;
        acc.w += w0 * h0.w + w1 * h1.w + w2 * h2.w + w3 * h3.w;
    }
    for (; j < end; ++j) {
        int2 cw = __ldg(&g_cw[j]);
        float wj = __int_as_float(cw.y);
        float4 hc = h4[(size_t)cw.x * (D / 4) + t];
        acc.x += wj * hc.x;
        acc.y += wj * hc.y;
        acc.z += wj * hc.z;
        acc.w += wj * hc.w;
    }
    ((float4*)out)[(size_t)v * (D / 4) + t] = acc;
}

// ---------------- tf32 tensor-core GEMM + bias + (relu(t)+t) epilogue ----------------
// C[N,256] = A[N,K] @ W[K,256]; BM=128 BN=128 BK=32, 8 warps (32x64 warp tiles)
// As uses XOR swizzle (row ^ chunk) to kill the 8-way store bank conflict.
template <int K>
__launch_bounds__(256)
__global__ void gemm_tf32(const float* __restrict__ A, const float* __restrict__ W,
                          const float* __restrict__ bias, float* __restrict__ C) {
    __shared__ __align__(16) unsigned As[8 * 128 * 4];   // [chunk][row^chunk][k%4]
    __shared__ __align__(16) unsigned Bs[32 * 136];      // [k][n] stride 136

    const int tid  = threadIdx.x;
    const int lane = tid & 31, wid = tid >> 5;
    const int g  = lane >> 2, t4 = lane & 3;
    const int m0 = blockIdx.x * 128, n0 = blockIdx.y * 128;
    const int wr = (wid & 3) * 32;     // warp row base
    const int wc = (wid >> 2) * 64;    // warp col base

    float acc[2][8][4];
    #pragma unroll
    for (int mt = 0; mt < 2; mt++)
        #pragma unroll
        for (int nt = 0; nt < 8; nt++)
            #pragma unroll
            for (int r = 0; r < 4; r++) acc[mt][nt][r] = 0.f;

    const int la_row = tid >> 3;       // 0..31 (m base; +i*32)
    const int la_ch  = tid & 7;        // k/4 chunk
    const int lb_k   = tid >> 5;       // 0..7  (k base; +i*8)
    const int lb_n   = (tid & 31) * 4; // n

    float4 aR[4], bR[4];

    auto fetch = [&](int k0) {
        #pragma unroll
        for (int i = 0; i < 4; i++) {
            int m = m0 + la_row + i * 32;
            aR[i] = (m < N_NODES)
                  ? *(const float4*)&A[(size_t)m * K + k0 + la_ch * 4]
                  : make_float4(0.f, 0.f, 0.f, 0.f);
        }
        #pragma unroll
        for (int i = 0; i < 4; i++) {
            int k = k0 + lb_k + i * 8;
            bR[i] = *(const float4*)&W[(size_t)k * 256 + n0 + lb_n];
        }
    };

    fetch(0);
    for (int k0 = 0; k0 < K; k0 += 32) {
        #pragma unroll
        for (int i = 0; i < 4; i++) {
            uint4 v = make_uint4(f2tf(aR[i].x), f2tf(aR[i].y), f2tf(aR[i].z), f2tf(aR[i].w));
            int row = la_row + i * 32;
            *(uint4*)&As[(la_ch * 128 + (row ^ la_ch)) * 4] = v;   // swizzled
        }
        #pragma unroll
        for (int i = 0; i < 4; i++) {
            uint4 v = make_uint4(f2tf(bR[i].x), f2tf(bR[i].y), f2tf(bR[i].z), f2tf(bR[i].w));
            *(uint4*)&Bs[(lb_k + i * 8) * 136 + lb_n] = v;
        }
        __syncthreads();
        if (k0 + 32 < K) fetch(k0 + 32);

        #pragma unroll
        for (int kk = 0; kk < 4; kk++) {
            const int c0 = 2 * kk, c1 = 2 * kk + 1;
            unsigned a[2][4];
            #pragma unroll
            for (int mt = 0; mt < 2; mt++) {
                int m = wr + mt * 16 + g;
                a[mt][0] = As[(c0 * 128 + (m ^ c0)) * 4 + t4];
                a[mt][1] = As[(c0 * 128 + ((m + 8) ^ c0)) * 4 + t4];
                a[mt][2] = As[(c1 * 128 + (m ^ c1)) * 4 + t4];
                a[mt][3] = As[(c1 * 128 + ((m + 8) ^ c1)) * 4 + t4];
            }
            #pragma unroll
            for (int nt = 0; nt < 8; nt++) {
                int n = wc + nt * 8 + g;
                unsigned b0 = Bs[(kk * 8 + t4) * 136 + n];
                unsigned b1 = Bs[(kk * 8 + t4 + 4) * 136 + n];
                #pragma unroll
                for (int mt = 0; mt < 2; mt++) {
                    asm volatile(
                        "mma.sync.aligned.m16n8k8.row.col.f32.tf32.tf32.f32 "
                        "{%0,%1,%2,%3}, {%4,%5,%6,%7}, {%8,%9}, {%0,%1,%2,%3};"
                        : "+f"(acc[mt][nt][0]), "+f"(acc[mt][nt][1]),
                          "+f"(acc[mt][nt][2]), "+f"(acc[mt][nt][3])
                        : "r"(a[mt][0]), "r"(a[mt][1]), "r"(a[mt][2]), "r"(a[mt][3]),
                          "r"(b0), "r"(b1));
                }
            }
        }
        __syncthreads();
    }

    // epilogue: bias + relu(t)+t
    #pragma unroll
    for (int mt = 0; mt < 2; mt++) {
        int r0 = m0 + wr + mt * 16 + g;
        #pragma unroll
        for (int nt = 0; nt < 8; nt++) {
            int n = n0 + wc + nt * 8 + 2 * t4;
            float bA = bias[n], bB = bias[n + 1];
            if (r0 < N_NODES) {
                float tx = acc[mt][nt][0] + bA;
                float ty = acc[mt][nt][1] + bB;
                *(float2*)&C[(size_t)r0 * 256 + n] =
                    make_float2(fmaxf(tx, 0.f) + tx, fmaxf(ty, 0.f) + ty);
            }
            int r1 = r0 + 8;
            if (r1 < N_NODES) {
                float tx = acc[mt][nt][2] + bA;
                float ty = acc[mt][nt][3] + bB;
                *(float2*)&C[(size_t)r1 * 256 + n] =
                    make_float2(fmaxf(tx, 0.f) + tx, fmaxf(ty, 0.f) + ty);
            }
        }
    }
}

// ---------------- LayerNorm over last dim (256), warp-shuffle reduction ----------------
__global__ void ln_kernel(const float* __restrict__ h, const float* __restrict__ lw,
                          const float* __restrict__ lb, float* __restrict__ out) {
    int row = blockIdx.x;
    int t = threadIdx.x, lane = t & 31, w = t >> 5;
    __shared__ float s1[8], s2[8];
    float v = h[(size_t)row * 256 + t];
    float a = v, b = v * v;
    #pragma unroll
    for (int off = 16; off > 0; off >>= 1) {
        a += __shfl_xor_sync(0xffffffffu, a, off);
        b += __shfl_xor_sync(0xffffffffu, b, off);
    }
    if (lane == 0) { s1[w] = a; s2[w] = b; }
    __syncthreads();
    float suma = 0.f, sumb = 0.f;
    #pragma unroll
    for (int i = 0; i < 8; i++) { suma += s1[i]; sumb += s2[i]; }
    float mean = suma * (1.f / 256.f);
    float var  = sumb * (1.f / 256.f) - mean * mean;
    out[(size_t)row * 256 + t] = (v - mean) * rsqrtf(var + 1e-6f) * lw[t] + lb[t];
}

__global__ void batchs_kernel(const int* __restrict__ b32, float* __restrict__ out) {
    int i = blockIdx.x * blockDim.x + threadIdx.x;
    if (i < N_NODES) {
        float bv = (float)idx_at(b32, g_mode32, i);
        out[i]           = bv;   // channel 0
        out[N_NODES + i] = bv;   // channel 1
    }
}

// ---------------- launcher ----------------
extern "C" void kernel_launch(void* const* d_in, const int* in_sizes, int n_in,
                              void* d_out, int out_size) {
    const float* x    = (const float*)d_in[0];
    const int*   e32  = (const int*)d_in[1];    // edge, int32 or int64 (auto-detected)
    const int*   b32  = (const int*)d_in[2];    // batch, same dtype
    const float* W0 = (const float*)d_in[3];
    const float* b0 = (const float*)d_in[4];
    const float* W1 = (const float*)d_in[5];
    const float* b1 = (const float*)d_in[6];
    const float* W2 = (const float*)d_in[7];
    const float* b2 = (const float*)d_in[8];
    const float* lnw = (const float*)d_in[9];
    const float* lnb = (const float*)d_in[10];
    float* out = (float*)d_out;

    float *p_aggX, *p_h, *p_agg, *p_h2, *p_agg2;
    cudaGetSymbolAddress((void**)&p_aggX, g_aggX);
    cudaGetSymbolAddress((void**)&p_h,    g_h);
    cudaGetSymbolAddress((void**)&p_agg,  g_agg);
    cudaGetSymbolAddress((void**)&p_h2,   g_h2);
    cudaGetSymbolAddress((void**)&p_agg2, g_agg2);

    // one-time stream/event setup (first call is the uncaptured correctness run)
    static cudaStream_t s2 = nullptr;
    static cudaEvent_t evF = nullptr, evJ = nullptr;
    if (!s2) {
        cudaStreamCreateWithFlags(&s2, cudaStreamNonBlocking);
        cudaEventCreateWithFlags(&evF, cudaEventDisableTiming);
        cudaEventCreateWithFlags(&evJ, cudaEventDisableTiming);
    }

    const int TB = 256;
    detect_kernel  <<<1, 1024>>>(e32);
    zero_cnt_kernel<<<(N_NODES + TB - 1) / TB, TB>>>();
    count_kernel   <<<(E_EDGES + TB - 1) / TB, TB>>>(e32);
    dinv_kernel    <<<(N_NODES + TB - 1) / TB, TB>>>();
    scan_kernel    <<<1, 1024>>>();
    fill_kernel    <<<(E_EDGES + TB - 1) / TB, TB>>>(e32);

    // shared layer-0 aggregation of x (128-dim)
    aggregate_kernel<128><<<N_NODES, 32>>>(x, p_aggX);

    // fork: channel 1 on s2
    cudaEventRecord(evF, 0);
    cudaStreamWaitEvent(s2, evF, 0);

    dim3 ggrid((N_NODES + 127) / 128, 2);

    // channel 1 chain (stream s2)
    batchs_kernel<<<(N_NODES + TB - 1) / TB, TB, 0, s2>>>(b32, out + (size_t)2 * N_NODES * 256);
    gemm_tf32<128><<<ggrid, 256, 0, s2>>>(p_aggX, W0 + (size_t)1 * 128 * 256, b0 + 256, p_h2);
    aggregate_kernel<256><<<N_NODES, 64, 0, s2>>>(p_h2, p_agg2);
    gemm_tf32<256><<<ggrid, 256, 0, s2>>>(p_agg2, W1 + (size_t)1 * 256 * 256, b1 + 256, p_h2);
    aggregate_kernel<256><<<N_NODES, 64, 0, s2>>>(p_h2, p_agg2);
    gemm_tf32<256><<<ggrid, 256, 0, s2>>>(p_agg2, W2 + (size_t)1 * 256 * 256, b2 + 256, p_h2);
    ln_kernel<<<N_NODES, 256, 0, s2>>>(p_h2, lnw, lnb, out + (size_t)1 * N_NODES * 256);
    cudaEventRecord(evJ, s2);

    // channel 0 chain (default stream)
    gemm_tf32<128><<<ggrid, 256>>>(p_aggX, W0, b0, p_h);
    aggregate_kernel<256><<<N_NODES, 64>>>(p_h, p_agg);
    gemm_tf32<256><<<ggrid, 256>>>(p_agg, W1, b1, p_h);
    aggregate_kernel<256><<<N_NODES, 64>>>(p_h, p_agg);
    gemm_tf32<256><<<ggrid, 256>>>(p_agg, W2, b2, p_h);
    ln_kernel<<<N_NODES, 256>>>(p_h, lnw, lnb, out);

    // join
    cudaStreamWaitEvent(0, evJ, 0);
}